// round 2
// baseline (speedup 1.0000x reference)
#include <cuda_runtime.h>
#include <math.h>

// ---------------------------------------------------------------------------
// GCNClassifier: 3x GCNConv (+leaky relu) + linear + log_softmax
// N = 100000 nodes, E = 1000000 edges
// dims: 64 -> 80 -> 40 -> 50 -> 10
// edge_index dtype: int32 (JAX x64 disabled downcasts the declared int64)
// ---------------------------------------------------------------------------

#define N_NODES 100000
#define MAX_DIM 80

// scratch (device globals; no allocation allowed)
__device__ float g_bufA[N_NODES * MAX_DIM];
__device__ float g_bufB[N_NODES * MAX_DIM];
__device__ float g_dinv[N_NODES];

// ---------------------------------------------------------------------------
// degree / dinv
// ---------------------------------------------------------------------------
__global__ void deg_init(float* deg, int n) {
    int i = blockIdx.x * blockDim.x + threadIdx.x;
    if (i < n) deg[i] = 1.0f;  // self-loop
}

__global__ void deg_count(const int* __restrict__ dst, float* deg, int E, int n) {
    int e = blockIdx.x * blockDim.x + threadIdx.x;
    if (e < E) {
        unsigned d = (unsigned)__ldg(&dst[e]);
        if (d < (unsigned)n) atomicAdd(&deg[d], 1.0f);
    }
}

__global__ void deg_finish(float* dinv, int n) {
    int i = blockIdx.x * blockDim.x + threadIdx.x;
    if (i < n) dinv[i] = rsqrtf(dinv[i]);
}

// ---------------------------------------------------------------------------
// GEMM: H[n, DOUT] = act(X[n, K]) @ W[K, DOUT]
// LEAKY: apply leaky_relu(0.01) to X elements on load (fuses prev activation)
// ---------------------------------------------------------------------------
template <int K, int DOUT, bool LEAKY>
__global__ void gemm_kernel(const float* __restrict__ X,
                            const float* __restrict__ W,
                            float* __restrict__ H, int n) {
    __shared__ float Ws[K * DOUT];
    for (int i = threadIdx.x; i < K * DOUT; i += blockDim.x) Ws[i] = W[i];
    __syncthreads();

    int idx = blockIdx.x * blockDim.x + threadIdx.x;
    int total = n * DOUT;
    if (idx >= total) return;
    int row = idx / DOUT;
    int j = idx - row * DOUT;

    const float* xr = X + (size_t)row * K;
    float acc = 0.0f;
#pragma unroll
    for (int k = 0; k < K; k++) {
        float v = __ldg(&xr[k]);
        if (LEAKY) v = (v > 0.0f) ? v : 0.01f * v;
        acc = fmaf(v, Ws[k * DOUT + j], acc);
    }
    H[idx] = acc;
}

// ---------------------------------------------------------------------------
// init agg: AGG[i,j] = H[i,j] * dinv[i]^2 + b[j]   (self-loop + bias)
// ---------------------------------------------------------------------------
template <int DIM>
__global__ void init_agg(const float* __restrict__ H,
                         const float* __restrict__ b,
                         const float* __restrict__ dinv,
                         float* __restrict__ AGG, int n) {
    int idx = blockIdx.x * blockDim.x + threadIdx.x;
    int total = n * DIM;
    if (idx >= total) return;
    int row = idx / DIM;
    int j = idx - row * DIM;
    float di = dinv[row];
    AGG[idx] = H[idx] * di * di + __ldg(&b[j]);
}

// ---------------------------------------------------------------------------
// edge scatter: AGG[dst,j] += H[src,j] * dinv[src] * dinv[dst]
// one thread per (edge, feature)
// ---------------------------------------------------------------------------
template <int DIM>
__global__ void aggregate(const float* __restrict__ H,
                          const int* __restrict__ src,
                          const int* __restrict__ dst,
                          const float* __restrict__ dinv,
                          float* __restrict__ AGG, int E, int n) {
    int idx = blockIdx.x * blockDim.x + threadIdx.x;
    int total = E * DIM;
    if (idx >= total) return;
    int e = idx / DIM;
    int j = idx - e * DIM;
    unsigned s = (unsigned)__ldg(&src[e]);
    unsigned d = (unsigned)__ldg(&dst[e]);
    if (s >= (unsigned)n || d >= (unsigned)n) return;
    float norm = __ldg(&dinv[s]) * __ldg(&dinv[d]);
    atomicAdd(&AGG[(size_t)d * DIM + j], __ldg(&H[(size_t)s * DIM + j]) * norm);
}

// ---------------------------------------------------------------------------
// final: logits = leaky(H3) @ Wl + bl, then log_softmax over 10 classes
// one thread per node
// ---------------------------------------------------------------------------
__global__ void final_kernel(const float* __restrict__ H,
                             const float* __restrict__ Wl,
                             const float* __restrict__ bl,
                             float* __restrict__ out, int n) {
    __shared__ float Ws[50 * 10];
    __shared__ float bs[10];
    for (int i = threadIdx.x; i < 500; i += blockDim.x) Ws[i] = Wl[i];
    if (threadIdx.x < 10) bs[threadIdx.x] = bl[threadIdx.x];
    __syncthreads();

    int i = blockIdx.x * blockDim.x + threadIdx.x;
    if (i >= n) return;

    float logits[10];
#pragma unroll
    for (int j = 0; j < 10; j++) logits[j] = bs[j];

    const float* hr = H + (size_t)i * 50;
#pragma unroll
    for (int k = 0; k < 50; k++) {
        float v = __ldg(&hr[k]);
        v = (v > 0.0f) ? v : 0.01f * v;
#pragma unroll
        for (int j = 0; j < 10; j++) logits[j] = fmaf(v, Ws[k * 10 + j], logits[j]);
    }

    float mx = logits[0];
#pragma unroll
    for (int j = 1; j < 10; j++) mx = fmaxf(mx, logits[j]);
    float s = 0.0f;
#pragma unroll
    for (int j = 0; j < 10; j++) s += __expf(logits[j] - mx);
    float lse = mx + __logf(s);
#pragma unroll
    for (int j = 0; j < 10; j++) out[(size_t)i * 10 + j] = logits[j] - lse;
}

// ---------------------------------------------------------------------------
// launch
// ---------------------------------------------------------------------------
static inline int cdiv(int a, int b) { return (a + b - 1) / b; }

extern "C" void kernel_launch(void* const* d_in, const int* in_sizes, int n_in,
                              void* d_out, int out_size) {
    const float* x = (const float*)d_in[0];
    const int* edge = (const int*)d_in[1];   // int32 (JAX downcast)
    const float* W1 = (const float*)d_in[2];
    const float* b1 = (const float*)d_in[3];
    const float* W2 = (const float*)d_in[4];
    const float* b2 = (const float*)d_in[5];
    const float* W3 = (const float*)d_in[6];
    const float* b3 = (const float*)d_in[7];
    const float* Wl = (const float*)d_in[8];
    const float* bl = (const float*)d_in[9];
    float* out = (float*)d_out;

    const int n = in_sizes[0] / 64;     // 100000
    const int E = in_sizes[1] / 2;      // 1000000
    const int* src = edge;
    const int* dst = edge + E;

    float* bufA;
    float* bufB;
    float* dinv;
    cudaGetSymbolAddress((void**)&bufA, g_bufA);
    cudaGetSymbolAddress((void**)&bufB, g_bufB);
    cudaGetSymbolAddress((void**)&dinv, g_dinv);

    const int T = 256;

    // degree -> dinv
    deg_init<<<cdiv(n, T), T>>>(dinv, n);
    deg_count<<<cdiv(E, T), T>>>(dst, dinv, E, n);
    deg_finish<<<cdiv(n, T), T>>>(dinv, n);

    // ---- layer 1: x(64) -> 80 ----
    gemm_kernel<64, 80, false><<<cdiv(n * 80, T), T>>>(x, W1, bufA, n);
    init_agg<80><<<cdiv(n * 80, T), T>>>(bufA, b1, dinv, bufB, n);
    aggregate<80><<<cdiv(E * 80, T), T>>>(bufA, src, dst, dinv, bufB, E, n);

    // ---- layer 2: 80 -> 40 (leaky fused into X read) ----
    gemm_kernel<80, 40, true><<<cdiv(n * 40, T), T>>>(bufB, W2, bufA, n);
    init_agg<40><<<cdiv(n * 40, T), T>>>(bufA, b2, dinv, bufB, n);
    aggregate<40><<<cdiv(E * 40, T), T>>>(bufA, src, dst, dinv, bufB, E, n);

    // ---- layer 3: 40 -> 50 ----
    gemm_kernel<40, 50, true><<<cdiv(n * 50, T), T>>>(bufB, W3, bufA, n);
    init_agg<50><<<cdiv(n * 50, T), T>>>(bufA, b3, dinv, bufB, n);
    aggregate<50><<<cdiv(E * 50, T), T>>>(bufA, src, dst, dinv, bufB, E, n);

    // ---- final linear + log_softmax (leaky fused) ----
    final_kernel<<<cdiv(n, T), T>>>(bufB, Wl, bl, out, n);
}

// round 4
// speedup vs baseline: 1.8076x; 1.8076x over previous
#include <cuda_runtime.h>
#include <math.h>

// ---------------------------------------------------------------------------
// GCNClassifier: 3x GCNConv (+leaky relu) + linear + log_softmax
// N = 100000, E = 1000000, dims 64 -> 80 -> 40 -> 50 -> 10
// ---------------------------------------------------------------------------

#define N_NODES 100000
#define MAX_DIM 80

// Three scratch buffers so GEMM read (X) and writes (Hs, AGG) never alias.
__device__ float g_bufA[N_NODES * MAX_DIM];  // Hs: h * dinv[row]  (messages)
__device__ float g_bufB[N_NODES * MAX_DIM];  // AGG / X ping
__device__ float g_bufC[N_NODES * MAX_DIM];  // AGG / X pong
__device__ float g_dinv[N_NODES];

static inline int cdiv(int a, int b) { return (a + b - 1) / b; }

// ---------------------------------------------------------------------------
// degree / dinv
// ---------------------------------------------------------------------------
__global__ void deg_init(float* deg, int n) {
    int i = blockIdx.x * blockDim.x + threadIdx.x;
    if (i < n) deg[i] = 1.0f;  // self-loop
}

__global__ void deg_count(const int* __restrict__ dst, float* deg, int E) {
    int e = blockIdx.x * blockDim.x + threadIdx.x;
    if (e < E) atomicAdd(&deg[__ldg(&dst[e])], 1.0f);
}

__global__ void deg_finish(float* dinv, int n) {
    int i = blockIdx.x * blockDim.x + threadIdx.x;
    if (i < n) dinv[i] = rsqrtf(dinv[i]);
}

// ---------------------------------------------------------------------------
// Fused GEMM + GCN epilogue.
//   acc = leaky(X[row]) @ W                    (packed f32x2 FMAs)
//   Hs[row]  = acc * dinv[row]                 (pre-scaled message buffer)
//   AGG[row] = acc * dinv[row]^2 + b           (self-loop + bias init)
// One thread per row, full-DOUT accumulators, X tile staged in smem.
// X, Hs, AGG must be pairwise non-aliasing buffers.
// ---------------------------------------------------------------------------
template <int K, int DOUT, bool LEAKY>
__global__ __launch_bounds__(64)
void gemm_fused(const float* __restrict__ X,
                const float* __restrict__ W,
                const float* __restrict__ b,
                const float* __restrict__ dinv,
                float* __restrict__ Hs,
                float* __restrict__ AGG, int n) {
    constexpr int ROWS = 64;
    constexpr int NP = DOUT / 2;  // packed pairs
    __shared__ __align__(16) float Ws[K * DOUT];
    __shared__ __align__(16) float Xs[ROWS * (K + 1)];
    __shared__ float bs[DOUT];

    const int row0 = blockIdx.x * ROWS;
    const int nrows = min(ROWS, n - row0);

    for (int i = threadIdx.x; i < K * DOUT; i += 64) Ws[i] = W[i];
    if (threadIdx.x < DOUT) bs[threadIdx.x] = b[threadIdx.x];
    if (DOUT > 64 && threadIdx.x + 64 < DOUT) bs[threadIdx.x + 64] = b[threadIdx.x + 64];

    for (int i = threadIdx.x; i < nrows * K; i += 64) {
        int r = i / K, c = i - r * K;
        float v = X[(size_t)(row0 + r) * K + c];
        if (LEAKY) v = (v > 0.0f) ? v : 0.01f * v;
        Xs[r * (K + 1) + c] = v;
    }
    __syncthreads();

    const int t = threadIdx.x;
    const int row = row0 + t;
    if (row >= n) return;

    unsigned long long acc[NP];
#pragma unroll
    for (int jp = 0; jp < NP; jp++) acc[jp] = 0ULL;

    const unsigned long long* W2 = (const unsigned long long*)Ws;
    const float* xr = &Xs[t * (K + 1)];

#pragma unroll 2
    for (int k = 0; k < K; k++) {
        float xv = xr[k];
        unsigned long long xp;
        asm("mov.b64 %0, {%1, %1};" : "=l"(xp) : "f"(xv));
        const unsigned long long* wr = &W2[k * NP];
#pragma unroll
        for (int jp = 0; jp < NP; jp++) {
            asm("fma.rn.f32x2 %0, %1, %2, %0;" : "+l"(acc[jp]) : "l"(xp), "l"(wr[jp]));
        }
    }

    const float di = dinv[row];
    const float di2 = di * di;
    float* hsr = Hs + (size_t)row * DOUT;
    float* agr = AGG + (size_t)row * DOUT;
#pragma unroll
    for (int jp = 0; jp < NP; jp++) {
        float lo, hi;
        asm("mov.b64 {%0, %1}, %2;" : "=f"(lo), "=f"(hi) : "l"(acc[jp]));
        hsr[2 * jp]     = lo * di;
        hsr[2 * jp + 1] = hi * di;
        agr[2 * jp]     = lo * di2 + bs[2 * jp];
        agr[2 * jp + 1] = hi * di2 + bs[2 * jp + 1];
    }
}

// ---------------------------------------------------------------------------
// Edge scatter, vectorized atomics.
//   AGG[dst] += Hs[src] * dinv[dst]        (Hs already carries dinv[src])
// ---------------------------------------------------------------------------
template <int NV>  // NV = DIM/4
__global__ void aggregate_v4(const float4* __restrict__ Hs,
                             const int* __restrict__ src,
                             const int* __restrict__ dst,
                             const float* __restrict__ dinv,
                             float4* __restrict__ AGG, int E) {
    int idx = blockIdx.x * blockDim.x + threadIdx.x;
    if (idx >= E * NV) return;
    int e = idx / NV;
    int g = idx - e * NV;
    int s = __ldg(&src[e]);
    int d = __ldg(&dst[e]);
    float nd = __ldg(&dinv[d]);
    float4 h = __ldg(&Hs[(size_t)s * NV + g]);
    float4 v = make_float4(h.x * nd, h.y * nd, h.z * nd, h.w * nd);
    atomicAdd(&AGG[(size_t)d * NV + g], v);
}

template <int NV>  // NV = DIM/2 (for 8B-aligned rows, dim 50)
__global__ void aggregate_v2(const float2* __restrict__ Hs,
                             const int* __restrict__ src,
                             const int* __restrict__ dst,
                             const float* __restrict__ dinv,
                             float2* __restrict__ AGG, int E) {
    int idx = blockIdx.x * blockDim.x + threadIdx.x;
    if (idx >= E * NV) return;
    int e = idx / NV;
    int g = idx - e * NV;
    int s = __ldg(&src[e]);
    int d = __ldg(&dst[e]);
    float nd = __ldg(&dinv[d]);
    float2 h = __ldg(&Hs[(size_t)s * NV + g]);
    float2 v = make_float2(h.x * nd, h.y * nd);
    atomicAdd(&AGG[(size_t)d * NV + g], v);
}

// ---------------------------------------------------------------------------
// final: logits = leaky(H3) @ Wl + bl, then log_softmax over 10 classes
// ---------------------------------------------------------------------------
__global__ void final_kernel(const float* __restrict__ H,
                             const float* __restrict__ Wl,
                             const float* __restrict__ bl,
                             float* __restrict__ out, int n) {
    __shared__ float Ws[50 * 10];
    __shared__ float bs[10];
    for (int i = threadIdx.x; i < 500; i += blockDim.x) Ws[i] = Wl[i];
    if (threadIdx.x < 10) bs[threadIdx.x] = bl[threadIdx.x];
    __syncthreads();

    int i = blockIdx.x * blockDim.x + threadIdx.x;
    if (i >= n) return;

    float logits[10];
#pragma unroll
    for (int j = 0; j < 10; j++) logits[j] = bs[j];

    const float* hr = H + (size_t)i * 50;
#pragma unroll
    for (int k = 0; k < 50; k++) {
        float v = __ldg(&hr[k]);
        v = (v > 0.0f) ? v : 0.01f * v;
#pragma unroll
        for (int j = 0; j < 10; j++) logits[j] = fmaf(v, Ws[k * 10 + j], logits[j]);
    }

    float mx = logits[0];
#pragma unroll
    for (int j = 1; j < 10; j++) mx = fmaxf(mx, logits[j]);
    float s = 0.0f;
#pragma unroll
    for (int j = 0; j < 10; j++) s += __expf(logits[j] - mx);
    float lse = mx + __logf(s);
#pragma unroll
    for (int j = 0; j < 10; j++) out[(size_t)i * 10 + j] = logits[j] - lse;
}

// ---------------------------------------------------------------------------
// launch
// ---------------------------------------------------------------------------
extern "C" void kernel_launch(void* const* d_in, const int* in_sizes, int n_in,
                              void* d_out, int out_size) {
    const float* x = (const float*)d_in[0];
    const int* edge = (const int*)d_in[1];  // int32 (JAX downcast)
    const float* W1 = (const float*)d_in[2];
    const float* b1 = (const float*)d_in[3];
    const float* W2 = (const float*)d_in[4];
    const float* b2 = (const float*)d_in[5];
    const float* W3 = (const float*)d_in[6];
    const float* b3 = (const float*)d_in[7];
    const float* Wl = (const float*)d_in[8];
    const float* bl = (const float*)d_in[9];
    float* out = (float*)d_out;

    const int n = in_sizes[0] / 64;  // 100000
    const int E = in_sizes[1] / 2;   // 1000000
    const int* src = edge;
    const int* dst = edge + E;

    float* bufA;
    float* bufB;
    float* bufC;
    float* dinv;
    cudaGetSymbolAddress((void**)&bufA, g_bufA);
    cudaGetSymbolAddress((void**)&bufB, g_bufB);
    cudaGetSymbolAddress((void**)&bufC, g_bufC);
    cudaGetSymbolAddress((void**)&dinv, g_dinv);

    const int T = 256;

    // degree -> dinv
    deg_init<<<cdiv(n, T), T>>>(dinv, n);
    deg_count<<<cdiv(E, T), T>>>(dst, dinv, E);
    deg_finish<<<cdiv(n, T), T>>>(dinv, n);

    // ---- layer 1: x(64) -> 80 ----   X=x, Hs=bufA, AGG=bufB
    gemm_fused<64, 80, false><<<cdiv(n, 64), 64>>>(x, W1, b1, dinv, bufA, bufB, n);
    aggregate_v4<20><<<cdiv(E * 20, T), T>>>((const float4*)bufA, src, dst, dinv,
                                             (float4*)bufB, E);

    // ---- layer 2: 80 -> 40 ----     X=bufB, Hs=bufA, AGG=bufC
    gemm_fused<80, 40, true><<<cdiv(n, 64), 64>>>(bufB, W2, b2, dinv, bufA, bufC, n);
    aggregate_v4<10><<<cdiv(E * 10, T), T>>>((const float4*)bufA, src, dst, dinv,
                                             (float4*)bufC, E);

    // ---- layer 3: 40 -> 50 ----     X=bufC, Hs=bufA, AGG=bufB
    gemm_fused<40, 50, true><<<cdiv(n, 64), 64>>>(bufC, W3, b3, dinv, bufA, bufB, n);
    aggregate_v2<25><<<cdiv(E * 25, T), T>>>((const float2*)bufA, src, dst, dinv,
                                             (float2*)bufB, E);

    // ---- final linear + log_softmax ----
    final_kernel<<<cdiv(n, T), T>>>(bufB, Wl, bl, out, n);
}

// round 5
// speedup vs baseline: 2.5170x; 1.3924x over previous
#include <cuda_runtime.h>
#include <math.h>

// ---------------------------------------------------------------------------
// GCNClassifier: 3x GCNConv (+leaky relu) + linear + log_softmax
// N = 100000, E = 1000000, dims 64 -> 80 -> 40 -> 50 -> 10
// ---------------------------------------------------------------------------

#define N_NODES 100000
#define MAX_DIM 80

// Three scratch buffers so GEMM read (X) and writes (Hs, AGG) never alias.
__device__ float g_bufA[N_NODES * MAX_DIM];  // Hs: h * dinv[row]  (messages)
__device__ float g_bufB[N_NODES * MAX_DIM];  // AGG / X ping
__device__ float g_bufC[N_NODES * MAX_DIM];  // AGG / X pong
__device__ float g_dinv[N_NODES];

static inline int cdiv(int a, int b) { return (a + b - 1) / b; }

// ---------------------------------------------------------------------------
// degree / dinv
// ---------------------------------------------------------------------------
__global__ void deg_init(float* deg, int n) {
    int i = blockIdx.x * blockDim.x + threadIdx.x;
    if (i < n) deg[i] = 1.0f;  // self-loop
}

__global__ void deg_count(const int* __restrict__ dst, float* deg, int E) {
    int e = blockIdx.x * blockDim.x + threadIdx.x;
    if (e < E) atomicAdd(&deg[__ldg(&dst[e])], 1.0f);
}

__global__ void deg_finish(float* dinv, int n) {
    int i = blockIdx.x * blockDim.x + threadIdx.x;
    if (i < n) dinv[i] = rsqrtf(dinv[i]);
}

// ---------------------------------------------------------------------------
// Register-tiled fused GEMM + GCN epilogue.
//   acc = leaky(X[rows]) @ W       TM x TN tile per thread, f32x2 FMAs
//   Hs  = acc * dinv[row]          (pre-scaled message buffer)
//   AGG = acc * dinv[row]^2 + b    (self-loop + bias init)
// X, Hs, AGG must be pairwise non-aliasing.
// ---------------------------------------------------------------------------
template <int K, int DOUT, int BM, int BK, int TM, int TN, int THREADS, bool LEAKY>
__global__ __launch_bounds__(THREADS)
void gemm_fused(const float* __restrict__ X,
                const float* __restrict__ W,
                const float* __restrict__ b,
                const float* __restrict__ dinv,
                float* __restrict__ Hs,
                float* __restrict__ AGG, int n) {
    constexpr int COLG = DOUT / TN;       // column groups
    constexpr int ROWG = THREADS / COLG;  // row groups
    constexpr int NP = TN / 2;            // packed f32x2 pairs per thread
    static_assert(COLG * TN == DOUT, "tn");
    static_assert(COLG * ROWG == THREADS, "thr");
    static_assert(ROWG * TM == BM, "bm");
    static_assert(K % BK == 0, "bk");

    __shared__ __align__(16) float Ws[K * DOUT];
    __shared__ __align__(16) float Xs[BM * (BK + 1)];

    const int tid = threadIdx.x;
    const int row0 = blockIdx.x * BM;
    const int nrows = min(BM, n - row0);

    for (int i = tid; i < K * DOUT; i += THREADS) Ws[i] = W[i];

    const int colg = tid % COLG;
    const int rowg = tid / COLG;
    const int col0 = colg * TN;
    const int r0 = rowg * TM;

    unsigned long long acc[TM][NP];
#pragma unroll
    for (int i = 0; i < TM; i++)
#pragma unroll
        for (int jp = 0; jp < NP; jp++) acc[i][jp] = 0ULL;

    for (int k0 = 0; k0 < K; k0 += BK) {
        __syncthreads();
        // stage X chunk [nrows x BK], coalesced, leaky fused
        for (int i = tid; i < nrows * BK; i += THREADS) {
            int r = i / BK, c = i - r * BK;
            float v = __ldg(&X[(size_t)(row0 + r) * K + k0 + c]);
            if (LEAKY) v = (v > 0.0f) ? v : 0.01f * v;
            Xs[r * (BK + 1) + c] = v;
        }
        __syncthreads();

#pragma unroll 4
        for (int k = 0; k < BK; k++) {
            unsigned long long wv[NP];
            const unsigned long long* wr =
                (const unsigned long long*)&Ws[(k0 + k) * DOUT + col0];
#pragma unroll
            for (int jp = 0; jp < NP; jp++) wv[jp] = wr[jp];
#pragma unroll
            for (int i = 0; i < TM; i++) {
                float xv = Xs[(r0 + i) * (BK + 1) + k];
                unsigned long long xp;
                asm("mov.b64 %0, {%1, %1};" : "=l"(xp) : "f"(xv));
#pragma unroll
                for (int jp = 0; jp < NP; jp++) {
                    asm("fma.rn.f32x2 %0, %1, %2, %0;"
                        : "+l"(acc[i][jp]) : "l"(xp), "l"(wv[jp]));
                }
            }
        }
    }

    // epilogue
#pragma unroll
    for (int i = 0; i < TM; i++) {
        int row = row0 + r0 + i;
        if (row >= n) break;
        float di = dinv[row];
        float di2 = di * di;
        float2* hsr = (float2*)(Hs + (size_t)row * DOUT + col0);
        float2* agr = (float2*)(AGG + (size_t)row * DOUT + col0);
#pragma unroll
        for (int jp = 0; jp < NP; jp++) {
            float lo, hi;
            asm("mov.b64 {%0, %1}, %2;" : "=f"(lo), "=f"(hi) : "l"(acc[i][jp]));
            float blo = __ldg(&b[col0 + 2 * jp]);
            float bhi = __ldg(&b[col0 + 2 * jp + 1]);
            hsr[jp] = make_float2(lo * di, hi * di);
            agr[jp] = make_float2(lo * di2 + blo, hi * di2 + bhi);
        }
    }
}

// ---------------------------------------------------------------------------
// Edge scatter, vectorized atomics.
//   AGG[dst] += Hs[src] * dinv[dst]        (Hs already carries dinv[src])
// ---------------------------------------------------------------------------
template <int NV>  // NV = DIM/4
__global__ void aggregate_v4(const float4* __restrict__ Hs,
                             const int* __restrict__ src,
                             const int* __restrict__ dst,
                             const float* __restrict__ dinv,
                             float4* __restrict__ AGG, int E) {
    int idx = blockIdx.x * blockDim.x + threadIdx.x;
    if (idx >= E * NV) return;
    int e = idx / NV;
    int g = idx - e * NV;
    int s = __ldg(&src[e]);
    int d = __ldg(&dst[e]);
    float nd = __ldg(&dinv[d]);
    float4 h = __ldg(&Hs[(size_t)s * NV + g]);
    float4 v = make_float4(h.x * nd, h.y * nd, h.z * nd, h.w * nd);
    atomicAdd(&AGG[(size_t)d * NV + g], v);
}

template <int NV>  // NV = DIM/2 (for 8B-aligned rows, dim 50)
__global__ void aggregate_v2(const float2* __restrict__ Hs,
                             const int* __restrict__ src,
                             const int* __restrict__ dst,
                             const float* __restrict__ dinv,
                             float2* __restrict__ AGG, int E) {
    int idx = blockIdx.x * blockDim.x + threadIdx.x;
    if (idx >= E * NV) return;
    int e = idx / NV;
    int g = idx - e * NV;
    int s = __ldg(&src[e]);
    int d = __ldg(&dst[e]);
    float nd = __ldg(&dinv[d]);
    float2 h = __ldg(&Hs[(size_t)s * NV + g]);
    float2 v = make_float2(h.x * nd, h.y * nd);
    atomicAdd(&AGG[(size_t)d * NV + g], v);
}

// ---------------------------------------------------------------------------
// final: logits = leaky(H3) @ Wl + bl, then log_softmax over 10 classes
// ---------------------------------------------------------------------------
__global__ void final_kernel(const float* __restrict__ H,
                             const float* __restrict__ Wl,
                             const float* __restrict__ bl,
                             float* __restrict__ out, int n) {
    __shared__ float Ws[50 * 10];
    __shared__ float bs[10];
    for (int i = threadIdx.x; i < 500; i += blockDim.x) Ws[i] = Wl[i];
    if (threadIdx.x < 10) bs[threadIdx.x] = bl[threadIdx.x];
    __syncthreads();

    int i = blockIdx.x * blockDim.x + threadIdx.x;
    if (i >= n) return;

    float logits[10];
#pragma unroll
    for (int j = 0; j < 10; j++) logits[j] = bs[j];

    const float* hr = H + (size_t)i * 50;
#pragma unroll
    for (int k = 0; k < 50; k++) {
        float v = __ldg(&hr[k]);
        v = (v > 0.0f) ? v : 0.01f * v;
#pragma unroll
        for (int j = 0; j < 10; j++) logits[j] = fmaf(v, Ws[k * 10 + j], logits[j]);
    }

    float mx = logits[0];
#pragma unroll
    for (int j = 1; j < 10; j++) mx = fmaxf(mx, logits[j]);
    float s = 0.0f;
#pragma unroll
    for (int j = 0; j < 10; j++) s += __expf(logits[j] - mx);
    float lse = mx + __logf(s);
#pragma unroll
    for (int j = 0; j < 10; j++) out[(size_t)i * 10 + j] = logits[j] - lse;
}

// ---------------------------------------------------------------------------
// launch
// ---------------------------------------------------------------------------
extern "C" void kernel_launch(void* const* d_in, const int* in_sizes, int n_in,
                              void* d_out, int out_size) {
    const float* x = (const float*)d_in[0];
    const int* edge = (const int*)d_in[1];  // int32 (JAX downcast)
    const float* W1 = (const float*)d_in[2];
    const float* b1 = (const float*)d_in[3];
    const float* W2 = (const float*)d_in[4];
    const float* b2 = (const float*)d_in[5];
    const float* W3 = (const float*)d_in[6];
    const float* b3 = (const float*)d_in[7];
    const float* Wl = (const float*)d_in[8];
    const float* bl = (const float*)d_in[9];
    float* out = (float*)d_out;

    const int n = in_sizes[0] / 64;  // 100000
    const int E = in_sizes[1] / 2;   // 1000000
    const int* src = edge;
    const int* dst = edge + E;

    float* bufA;
    float* bufB;
    float* bufC;
    float* dinv;
    cudaGetSymbolAddress((void**)&bufA, g_bufA);
    cudaGetSymbolAddress((void**)&bufB, g_bufB);
    cudaGetSymbolAddress((void**)&bufC, g_bufC);
    cudaGetSymbolAddress((void**)&dinv, g_dinv);

    const int T = 256;

    // degree -> dinv
    deg_init<<<cdiv(n, T), T>>>(dinv, n);
    deg_count<<<cdiv(E, T), T>>>(dst, dinv, E);
    deg_finish<<<cdiv(n, T), T>>>(dinv, n);

    // ---- layer 1: x(64) -> 80 ----   X=x, Hs=bufA, AGG=bufB
    // K=64 DOUT=80 BM=128 BK=32 TM=8 TN=10 THREADS=128
    gemm_fused<64, 80, 128, 32, 8, 10, 128, false>
        <<<cdiv(n, 128), 128>>>(x, W1, b1, dinv, bufA, bufB, n);
    aggregate_v4<20><<<cdiv(E * 20, T), T>>>((const float4*)bufA, src, dst, dinv,
                                             (float4*)bufB, E);

    // ---- layer 2: 80 -> 40 ----     X=bufB, Hs=bufA, AGG=bufC
    // K=80 DOUT=40 BM=256 BK=20 TM=8 TN=10 THREADS=128
    gemm_fused<80, 40, 256, 20, 8, 10, 128, true>
        <<<cdiv(n, 256), 128>>>(bufB, W2, b2, dinv, bufA, bufC, n);
    aggregate_v4<10><<<cdiv(E * 10, T), T>>>((const float4*)bufA, src, dst, dinv,
                                             (float4*)bufC, E);

    // ---- layer 3: 40 -> 50 ----     X=bufC, Hs=bufA, AGG=bufB
    // K=40 DOUT=50 BM=256 BK=20 TM=8 TN=10 THREADS=160
    gemm_fused<40, 50, 256, 20, 8, 10, 160, true>
        <<<cdiv(n, 256), 160>>>(bufC, W3, b3, dinv, bufA, bufB, n);
    aggregate_v2<25><<<cdiv(E * 25, T), T>>>((const float2*)bufA, src, dst, dinv,
                                             (float2*)bufB, E);

    // ---- final linear + log_softmax ----
    final_kernel<<<cdiv(n, T), T>>>(bufB, Wl, bl, out, n);
}

// round 6
// speedup vs baseline: 3.5152x; 1.3966x over previous
#include <cuda_runtime.h>
#include <math.h>

// ---------------------------------------------------------------------------
// GCNClassifier: 3x GCNConv (+leaky relu) + linear + log_softmax
// N = 100000, E = 1000000, dims 64 -> 80 -> 40 -> 50 -> 10
// Strategy: per-call CSR build (by dst), register-gather aggregation (no
// float atomics), register-tiled fused GEMMs with f32x2 FMAs.
// ---------------------------------------------------------------------------

#define N_NODES 100000
#define E_MAX   1000000
#define MAX_DIM 80
#define SCAN_B  1024
#define NB_MAX  128   // cdiv(100000,1024)=98

// scratch (device globals; no allocation allowed)
__device__ float g_bufA[N_NODES * MAX_DIM];  // Hs: h * dinv[row]
__device__ float g_bufB[N_NODES * MAX_DIM];  // AGG / X ping
__device__ float g_bufC[N_NODES * MAX_DIM];  // AGG / X pong
__device__ float g_dinv[N_NODES];
__device__ int   g_deg[N_NODES];
__device__ int   g_incl[N_NODES];
__device__ int   g_bsum[NB_MAX];
__device__ int   g_boff[NB_MAX];
__device__ int   g_off[N_NODES + 1];
__device__ int   g_cur[N_NODES];
__device__ int   g_csrc[E_MAX];

static inline int cdiv(int a, int b) { return (a + b - 1) / b; }

// ---------------------------------------------------------------------------
// CSR build: histogram -> scan -> scatter      (+ dinv = rsqrt(deg+1))
// ---------------------------------------------------------------------------
__global__ void deg_zero(int* deg, int n) {
    int i = blockIdx.x * blockDim.x + threadIdx.x;
    if (i < n) deg[i] = 0;
}

__global__ void deg_hist(const int* __restrict__ dst, int* deg, int E) {
    int e = blockIdx.x * blockDim.x + threadIdx.x;
    if (e < E) atomicAdd(&deg[__ldg(&dst[e])], 1);
}

__global__ void scan_block(const int* __restrict__ deg, int* incl, int* bsum, int n) {
    __shared__ int sh[SCAN_B];
    int i = blockIdx.x * SCAN_B + threadIdx.x;
    sh[threadIdx.x] = (i < n) ? deg[i] : 0;
    __syncthreads();
#pragma unroll
    for (int ofs = 1; ofs < SCAN_B; ofs <<= 1) {
        int t = (threadIdx.x >= ofs) ? sh[threadIdx.x - ofs] : 0;
        __syncthreads();
        sh[threadIdx.x] += t;
        __syncthreads();
    }
    if (i < n) incl[i] = sh[threadIdx.x];
    if (threadIdx.x == SCAN_B - 1) bsum[blockIdx.x] = sh[SCAN_B - 1];
}

__global__ void scan_bsums(const int* __restrict__ bsum, int* boff, int nb) {
    if (threadIdx.x == 0 && blockIdx.x == 0) {
        int run = 0;
        for (int i = 0; i < nb; i++) { boff[i] = run; run += bsum[i]; }
    }
}

__global__ void finish_offsets(const int* __restrict__ deg,
                               const int* __restrict__ incl,
                               const int* __restrict__ boff,
                               int* off, int* cur, float* dinv, int n, int E) {
    int i = blockIdx.x * blockDim.x + threadIdx.x;
    if (i < n) {
        int o = incl[i] - deg[i] + boff[i >> 10];
        off[i] = o;
        cur[i] = o;
        dinv[i] = rsqrtf((float)deg[i] + 1.0f);
        if (i == 0) off[n] = E;
    }
}

__global__ void csr_scatter(const int* __restrict__ src,
                            const int* __restrict__ dst,
                            int* cur, int* csrc, int E) {
    int e = blockIdx.x * blockDim.x + threadIdx.x;
    if (e < E) {
        int d = __ldg(&dst[e]);
        int pos = atomicAdd(&cur[d], 1);
        csrc[pos] = __ldg(&src[e]);
    }
}

// ---------------------------------------------------------------------------
// Register-tiled fused GEMM + GCN epilogue.
//   acc = leaky(X[rows]) @ W       TM x TN tile per thread, f32x2 FMAs
//   Hs  = acc * dinv[row]          (pre-scaled message buffer)
//   AGG = acc * dinv[row]^2 + b    (self-loop + bias init)
// X, Hs, AGG must be pairwise non-aliasing.
// ---------------------------------------------------------------------------
template <int K, int DOUT, int BM, int BK, int TM, int TN, int THREADS, bool LEAKY>
__global__ __launch_bounds__(THREADS)
void gemm_fused(const float* __restrict__ X,
                const float* __restrict__ W,
                const float* __restrict__ b,
                const float* __restrict__ dinv,
                float* __restrict__ Hs,
                float* __restrict__ AGG, int n) {
    constexpr int COLG = DOUT / TN;
    constexpr int ROWG = THREADS / COLG;
    constexpr int NP = TN / 2;
    static_assert(COLG * TN == DOUT, "tn");
    static_assert(COLG * ROWG == THREADS, "thr");
    static_assert(ROWG * TM == BM, "bm");
    static_assert(K % BK == 0, "bk");

    __shared__ __align__(16) float Ws[K * DOUT];
    __shared__ __align__(16) float Xs[BM * (BK + 1)];

    const int tid = threadIdx.x;
    const int row0 = blockIdx.x * BM;
    const int nrows = min(BM, n - row0);

    for (int i = tid; i < K * DOUT; i += THREADS) Ws[i] = W[i];

    const int colg = tid % COLG;
    const int rowg = tid / COLG;
    const int col0 = colg * TN;
    const int r0 = rowg * TM;

    unsigned long long acc[TM][NP];
#pragma unroll
    for (int i = 0; i < TM; i++)
#pragma unroll
        for (int jp = 0; jp < NP; jp++) acc[i][jp] = 0ULL;

    for (int k0 = 0; k0 < K; k0 += BK) {
        __syncthreads();
        for (int i = tid; i < nrows * BK; i += THREADS) {
            int r = i / BK, c = i - r * BK;
            float v = __ldg(&X[(size_t)(row0 + r) * K + k0 + c]);
            if (LEAKY) v = (v > 0.0f) ? v : 0.01f * v;
            Xs[r * (BK + 1) + c] = v;
        }
        __syncthreads();

#pragma unroll 4
        for (int k = 0; k < BK; k++) {
            unsigned long long wv[NP];
            const unsigned long long* wr =
                (const unsigned long long*)&Ws[(k0 + k) * DOUT + col0];
#pragma unroll
            for (int jp = 0; jp < NP; jp++) wv[jp] = wr[jp];
#pragma unroll
            for (int i = 0; i < TM; i++) {
                float xv = Xs[(r0 + i) * (BK + 1) + k];
                unsigned long long xp;
                asm("mov.b64 %0, {%1, %1};" : "=l"(xp) : "f"(xv));
#pragma unroll
                for (int jp = 0; jp < NP; jp++) {
                    asm("fma.rn.f32x2 %0, %1, %2, %0;"
                        : "+l"(acc[i][jp]) : "l"(xp), "l"(wv[jp]));
                }
            }
        }
    }

#pragma unroll
    for (int i = 0; i < TM; i++) {
        int row = row0 + r0 + i;
        if (row >= n) break;
        float di = dinv[row];
        float di2 = di * di;
        float2* hsr = (float2*)(Hs + (size_t)row * DOUT + col0);
        float2* agr = (float2*)(AGG + (size_t)row * DOUT + col0);
#pragma unroll
        for (int jp = 0; jp < NP; jp++) {
            float lo, hi;
            asm("mov.b64 {%0, %1}, %2;" : "=f"(lo), "=f"(hi) : "l"(acc[i][jp]));
            float blo = __ldg(&b[col0 + 2 * jp]);
            float bhi = __ldg(&b[col0 + 2 * jp + 1]);
            hsr[jp] = make_float2(lo * di, hi * di);
            agr[jp] = make_float2(lo * di2 + blo, hi * di2 + bhi);
        }
    }
}

// ---------------------------------------------------------------------------
// CSR gather-aggregate (no atomics):
//   AGG[node] += (sum over incoming src of Hs[src]) * dinv[node]
// one thread per (node, feature group); AGG pre-holds self-loop + bias.
// ---------------------------------------------------------------------------
template <int NV>  // NV = DIM/4
__global__ void agg_csr_v4(const float4* __restrict__ Hs,
                           const int* __restrict__ off,
                           const int* __restrict__ csrc,
                           const float* __restrict__ dinv,
                           float4* __restrict__ AGG, int n) {
    int idx = blockIdx.x * blockDim.x + threadIdx.x;
    if (idx >= n * NV) return;
    int node = idx / NV;
    int g = idx - node * NV;
    int e = __ldg(&off[node]);
    int e1 = __ldg(&off[node + 1]);
    float4 sum = make_float4(0.f, 0.f, 0.f, 0.f);
    for (; e + 1 < e1; e += 2) {
        int s0 = __ldg(&csrc[e]);
        int s1 = __ldg(&csrc[e + 1]);
        float4 h0 = __ldg(&Hs[(size_t)s0 * NV + g]);
        float4 h1 = __ldg(&Hs[(size_t)s1 * NV + g]);
        sum.x += h0.x + h1.x; sum.y += h0.y + h1.y;
        sum.z += h0.z + h1.z; sum.w += h0.w + h1.w;
    }
    if (e < e1) {
        int s0 = __ldg(&csrc[e]);
        float4 h0 = __ldg(&Hs[(size_t)s0 * NV + g]);
        sum.x += h0.x; sum.y += h0.y; sum.z += h0.z; sum.w += h0.w;
    }
    float nd = __ldg(&dinv[node]);
    float4 acc = AGG[(size_t)node * NV + g];
    acc.x = fmaf(sum.x, nd, acc.x);
    acc.y = fmaf(sum.y, nd, acc.y);
    acc.z = fmaf(sum.z, nd, acc.z);
    acc.w = fmaf(sum.w, nd, acc.w);
    AGG[(size_t)node * NV + g] = acc;
}

template <int NV>  // NV = DIM/2 (8B-aligned rows, dim 50)
__global__ void agg_csr_v2(const float2* __restrict__ Hs,
                           const int* __restrict__ off,
                           const int* __restrict__ csrc,
                           const float* __restrict__ dinv,
                           float2* __restrict__ AGG, int n) {
    int idx = blockIdx.x * blockDim.x + threadIdx.x;
    if (idx >= n * NV) return;
    int node = idx / NV;
    int g = idx - node * NV;
    int e = __ldg(&off[node]);
    int e1 = __ldg(&off[node + 1]);
    float2 sum = make_float2(0.f, 0.f);
    for (; e + 1 < e1; e += 2) {
        int s0 = __ldg(&csrc[e]);
        int s1 = __ldg(&csrc[e + 1]);
        float2 h0 = __ldg(&Hs[(size_t)s0 * NV + g]);
        float2 h1 = __ldg(&Hs[(size_t)s1 * NV + g]);
        sum.x += h0.x + h1.x; sum.y += h0.y + h1.y;
    }
    if (e < e1) {
        int s0 = __ldg(&csrc[e]);
        float2 h0 = __ldg(&Hs[(size_t)s0 * NV + g]);
        sum.x += h0.x; sum.y += h0.y;
    }
    float nd = __ldg(&dinv[node]);
    float2 acc = AGG[(size_t)node * NV + g];
    acc.x = fmaf(sum.x, nd, acc.x);
    acc.y = fmaf(sum.y, nd, acc.y);
    AGG[(size_t)node * NV + g] = acc;
}

// ---------------------------------------------------------------------------
// final: logits = leaky(H3) @ Wl + bl, then log_softmax over 10 classes
// ---------------------------------------------------------------------------
__global__ void final_kernel(const float* __restrict__ H,
                             const float* __restrict__ Wl,
                             const float* __restrict__ bl,
                             float* __restrict__ out, int n) {
    __shared__ float Ws[50 * 10];
    __shared__ float bs[10];
    for (int i = threadIdx.x; i < 500; i += blockDim.x) Ws[i] = Wl[i];
    if (threadIdx.x < 10) bs[threadIdx.x] = bl[threadIdx.x];
    __syncthreads();

    int i = blockIdx.x * blockDim.x + threadIdx.x;
    if (i >= n) return;

    float logits[10];
#pragma unroll
    for (int j = 0; j < 10; j++) logits[j] = bs[j];

    const float* hr = H + (size_t)i * 50;
#pragma unroll
    for (int k = 0; k < 50; k++) {
        float v = __ldg(&hr[k]);
        v = (v > 0.0f) ? v : 0.01f * v;
#pragma unroll
        for (int j = 0; j < 10; j++) logits[j] = fmaf(v, Ws[k * 10 + j], logits[j]);
    }

    float mx = logits[0];
#pragma unroll
    for (int j = 1; j < 10; j++) mx = fmaxf(mx, logits[j]);
    float s = 0.0f;
#pragma unroll
    for (int j = 0; j < 10; j++) s += __expf(logits[j] - mx);
    float lse = mx + __logf(s);
#pragma unroll
    for (int j = 0; j < 10; j++) out[(size_t)i * 10 + j] = logits[j] - lse;
}

// ---------------------------------------------------------------------------
// launch
// ---------------------------------------------------------------------------
extern "C" void kernel_launch(void* const* d_in, const int* in_sizes, int n_in,
                              void* d_out, int out_size) {
    const float* x = (const float*)d_in[0];
    const int* edge = (const int*)d_in[1];  // int32 (JAX downcast)
    const float* W1 = (const float*)d_in[2];
    const float* b1 = (const float*)d_in[3];
    const float* W2 = (const float*)d_in[4];
    const float* b2 = (const float*)d_in[5];
    const float* W3 = (const float*)d_in[6];
    const float* b3 = (const float*)d_in[7];
    const float* Wl = (const float*)d_in[8];
    const float* bl = (const float*)d_in[9];
    float* out = (float*)d_out;

    const int n = in_sizes[0] / 64;  // 100000
    const int E = in_sizes[1] / 2;   // 1000000
    const int* src = edge;
    const int* dst = edge + E;

    float *bufA, *bufB, *bufC, *dinv;
    int *deg, *incl, *bsum, *boff, *off, *cur, *csrc;
    cudaGetSymbolAddress((void**)&bufA, g_bufA);
    cudaGetSymbolAddress((void**)&bufB, g_bufB);
    cudaGetSymbolAddress((void**)&bufC, g_bufC);
    cudaGetSymbolAddress((void**)&dinv, g_dinv);
    cudaGetSymbolAddress((void**)&deg, g_deg);
    cudaGetSymbolAddress((void**)&incl, g_incl);
    cudaGetSymbolAddress((void**)&bsum, g_bsum);
    cudaGetSymbolAddress((void**)&boff, g_boff);
    cudaGetSymbolAddress((void**)&off, g_off);
    cudaGetSymbolAddress((void**)&cur, g_cur);
    cudaGetSymbolAddress((void**)&csrc, g_csrc);

    const int T = 256;
    const int nb = cdiv(n, SCAN_B);

    // ---- CSR build (by dst) + dinv ----
    deg_zero<<<cdiv(n, T), T>>>(deg, n);
    deg_hist<<<cdiv(E, T), T>>>(dst, deg, E);
    scan_block<<<nb, SCAN_B>>>(deg, incl, bsum, n);
    scan_bsums<<<1, 32>>>(bsum, boff, nb);
    finish_offsets<<<cdiv(n, T), T>>>(deg, incl, boff, off, cur, dinv, n, E);
    csr_scatter<<<cdiv(E, T), T>>>(src, dst, cur, csrc, E);

    // ---- layer 1: x(64) -> 80 ----   X=x, Hs=bufA, AGG=bufB
    gemm_fused<64, 80, 64, 32, 4, 10, 128, false>
        <<<cdiv(n, 64), 128>>>(x, W1, b1, dinv, bufA, bufB, n);
    agg_csr_v4<20><<<cdiv(n * 20, T), T>>>((const float4*)bufA, off, csrc, dinv,
                                           (float4*)bufB, n);

    // ---- layer 2: 80 -> 40 ----     X=bufB, Hs=bufA, AGG=bufC
    gemm_fused<80, 40, 128, 20, 4, 10, 128, true>
        <<<cdiv(n, 128), 128>>>(bufB, W2, b2, dinv, bufA, bufC, n);
    agg_csr_v4<10><<<cdiv(n * 10, T), T>>>((const float4*)bufA, off, csrc, dinv,
                                           (float4*)bufC, n);

    // ---- layer 3: 40 -> 50 ----     X=bufC, Hs=bufA, AGG=bufB
    gemm_fused<40, 50, 128, 20, 4, 10, 160, true>
        <<<cdiv(n, 128), 160>>>(bufC, W3, b3, dinv, bufA, bufB, n);
    agg_csr_v2<25><<<cdiv(n * 25, T), T>>>((const float2*)bufA, off, csrc, dinv,
                                           (float2*)bufB, n);

    // ---- final linear + log_softmax ----
    final_kernel<<<cdiv(n, T), T>>>(bufB, Wl, bl, out, n);
}

// round 7
// speedup vs baseline: 3.5775x; 1.0177x over previous
#include <cuda_runtime.h>
#include <math.h>

// ---------------------------------------------------------------------------
// GCNClassifier: 3x GCNConv (+leaky relu) + linear + log_softmax
// N = 100000, E = 1000000, dims 64 -> 80 -> 40 -> 50 -> 10
// Strategy: per-call CSR build (by dst), register-gather aggregation (no
// float atomics), register-tiled fused GEMMs with f32x2 FMAs.
// Layer 1 aggregates BEFORE the GEMM (input dim 64 < output dim 80).
// ---------------------------------------------------------------------------

#define N_NODES 100000
#define E_MAX   1000000
#define MAX_DIM 80
#define SCAN_B  1024
#define NB_MAX  128   // cdiv(100000,1024)=98

// scratch (device globals; no allocation allowed)
__device__ float g_bufA[N_NODES * MAX_DIM];
__device__ float g_bufB[N_NODES * MAX_DIM];
__device__ float g_bufC[N_NODES * MAX_DIM];
__device__ float g_dinv[N_NODES];
__device__ int   g_deg[N_NODES];
__device__ int   g_incl[N_NODES];
__device__ int   g_bsum[NB_MAX];
__device__ int   g_boff[NB_MAX];
__device__ int   g_off[N_NODES + 1];
__device__ int   g_cur[N_NODES];
__device__ int   g_csrc[E_MAX];

static inline int cdiv(int a, int b) { return (a + b - 1) / b; }

// ---------------------------------------------------------------------------
// CSR build: histogram -> scan -> scatter      (+ dinv = rsqrt(deg+1))
// ---------------------------------------------------------------------------
__global__ void deg_zero(int* deg, int n) {
    int i = blockIdx.x * blockDim.x + threadIdx.x;
    if (i < n) deg[i] = 0;
}

__global__ void deg_hist(const int* __restrict__ dst, int* deg, int E) {
    int e = blockIdx.x * blockDim.x + threadIdx.x;
    if (e < E) atomicAdd(&deg[__ldg(&dst[e])], 1);
}

__global__ void scan_block(const int* __restrict__ deg, int* incl, int* bsum, int n) {
    __shared__ int sh[SCAN_B];
    int i = blockIdx.x * SCAN_B + threadIdx.x;
    sh[threadIdx.x] = (i < n) ? deg[i] : 0;
    __syncthreads();
#pragma unroll
    for (int ofs = 1; ofs < SCAN_B; ofs <<= 1) {
        int t = (threadIdx.x >= ofs) ? sh[threadIdx.x - ofs] : 0;
        __syncthreads();
        sh[threadIdx.x] += t;
        __syncthreads();
    }
    if (i < n) incl[i] = sh[threadIdx.x];
    if (threadIdx.x == SCAN_B - 1) bsum[blockIdx.x] = sh[SCAN_B - 1];
}

// parallel exclusive scan over <=128 block sums, one 128-thread block
__global__ void scan_bsums(const int* __restrict__ bsum, int* boff, int nb) {
    __shared__ int sh[128];
    int t = threadIdx.x;
    int v = (t < nb) ? bsum[t] : 0;
    sh[t] = v;
    __syncthreads();
#pragma unroll
    for (int ofs = 1; ofs < 128; ofs <<= 1) {
        int u = (t >= ofs) ? sh[t - ofs] : 0;
        __syncthreads();
        sh[t] += u;
        __syncthreads();
    }
    if (t < nb) boff[t] = sh[t] - v;  // exclusive
}

__global__ void finish_offsets(const int* __restrict__ deg,
                               const int* __restrict__ incl,
                               const int* __restrict__ boff,
                               int* off, int* cur, float* dinv, int n, int E) {
    int i = blockIdx.x * blockDim.x + threadIdx.x;
    if (i < n) {
        int o = incl[i] - deg[i] + boff[i >> 10];
        off[i] = o;
        cur[i] = o;
        dinv[i] = rsqrtf((float)deg[i] + 1.0f);
        if (i == 0) off[n] = E;
    }
}

__global__ void csr_scatter(const int* __restrict__ src,
                            const int* __restrict__ dst,
                            int* cur, int* csrc, int E) {
    int e = blockIdx.x * blockDim.x + threadIdx.x;
    if (e < E) {
        int d = __ldg(&dst[e]);
        int pos = atomicAdd(&cur[d], 1);
        csrc[pos] = __ldg(&src[e]);
    }
}

// ---------------------------------------------------------------------------
// Layer-1 aggregate-first: Z[i] = dinv[i]*(sum_s dinv[s]*x[s]) + dinv[i]^2*x[i]
// one thread per (node, float4 group), NV = 64/4 = 16
// ---------------------------------------------------------------------------
__global__ void agg_x_v4(const float4* __restrict__ X4,
                         const int* __restrict__ off,
                         const int* __restrict__ csrc,
                         const float* __restrict__ dinv,
                         float4* __restrict__ Z, int n) {
    constexpr int NV = 16;
    int idx = blockIdx.x * blockDim.x + threadIdx.x;
    if (idx >= n * NV) return;
    int node = idx / NV;
    int g = idx - node * NV;
    int e = __ldg(&off[node]);
    int e1 = __ldg(&off[node + 1]);
    float4 sum = make_float4(0.f, 0.f, 0.f, 0.f);
    for (; e + 1 < e1; e += 2) {
        int s0 = __ldg(&csrc[e]);
        int s1 = __ldg(&csrc[e + 1]);
        float d0 = __ldg(&dinv[s0]);
        float d1 = __ldg(&dinv[s1]);
        float4 h0 = __ldg(&X4[(size_t)s0 * NV + g]);
        float4 h1 = __ldg(&X4[(size_t)s1 * NV + g]);
        sum.x = fmaf(h0.x, d0, fmaf(h1.x, d1, sum.x));
        sum.y = fmaf(h0.y, d0, fmaf(h1.y, d1, sum.y));
        sum.z = fmaf(h0.z, d0, fmaf(h1.z, d1, sum.z));
        sum.w = fmaf(h0.w, d0, fmaf(h1.w, d1, sum.w));
    }
    if (e < e1) {
        int s0 = __ldg(&csrc[e]);
        float d0 = __ldg(&dinv[s0]);
        float4 h0 = __ldg(&X4[(size_t)s0 * NV + g]);
        sum.x = fmaf(h0.x, d0, sum.x);
        sum.y = fmaf(h0.y, d0, sum.y);
        sum.z = fmaf(h0.z, d0, sum.z);
        sum.w = fmaf(h0.w, d0, sum.w);
    }
    float di = __ldg(&dinv[node]);
    float di2 = di * di;
    float4 self = __ldg(&X4[(size_t)node * NV + g]);
    float4 z;
    z.x = fmaf(sum.x, di, self.x * di2);
    z.y = fmaf(sum.y, di, self.y * di2);
    z.z = fmaf(sum.z, di, self.z * di2);
    z.w = fmaf(sum.w, di, self.w * di2);
    Z[(size_t)node * NV + g] = z;
}

// ---------------------------------------------------------------------------
// Register-tiled fused GEMM.
//   acc = leaky?(X[rows]) @ W       TM x TN tile per thread, f32x2 FMAs
// GCNEPI=true:  Hs = acc*dinv, AGG = acc*dinv^2 + b   (agg-after layers)
// GCNEPI=false: OUT(=AGG param) = acc + b             (plain)
// X and outputs must not alias.
// ---------------------------------------------------------------------------
template <int K, int DOUT, int BM, int BK, int TM, int TN, int THREADS,
          bool LEAKY, bool GCNEPI>
__global__ __launch_bounds__(THREADS)
void gemm_fused(const float* __restrict__ X,
                const float* __restrict__ W,
                const float* __restrict__ b,
                const float* __restrict__ dinv,
                float* __restrict__ Hs,
                float* __restrict__ AGG, int n) {
    constexpr int COLG = DOUT / TN;
    constexpr int ROWG = THREADS / COLG;
    constexpr int NP = TN / 2;
    static_assert(COLG * TN == DOUT, "tn");
    static_assert(COLG * ROWG == THREADS, "thr");
    static_assert(ROWG * TM == BM, "bm");
    static_assert(K % BK == 0, "bk");

    __shared__ __align__(16) float Ws[K * DOUT];
    __shared__ __align__(16) float Xs[BM * (BK + 1)];

    const int tid = threadIdx.x;
    const int row0 = blockIdx.x * BM;
    const int nrows = min(BM, n - row0);

    for (int i = tid; i < K * DOUT; i += THREADS) Ws[i] = W[i];

    const int colg = tid % COLG;
    const int rowg = tid / COLG;
    const int col0 = colg * TN;
    const int r0 = rowg * TM;

    unsigned long long acc[TM][NP];
#pragma unroll
    for (int i = 0; i < TM; i++)
#pragma unroll
        for (int jp = 0; jp < NP; jp++) acc[i][jp] = 0ULL;

    for (int k0 = 0; k0 < K; k0 += BK) {
        __syncthreads();
        for (int i = tid; i < nrows * BK; i += THREADS) {
            int r = i / BK, c = i - r * BK;
            float v = __ldg(&X[(size_t)(row0 + r) * K + k0 + c]);
            if (LEAKY) v = (v > 0.0f) ? v : 0.01f * v;
            Xs[r * (BK + 1) + c] = v;
        }
        __syncthreads();

#pragma unroll 4
        for (int k = 0; k < BK; k++) {
            unsigned long long wv[NP];
            const unsigned long long* wr =
                (const unsigned long long*)&Ws[(k0 + k) * DOUT + col0];
#pragma unroll
            for (int jp = 0; jp < NP; jp++) wv[jp] = wr[jp];
#pragma unroll
            for (int i = 0; i < TM; i++) {
                float xv = Xs[(r0 + i) * (BK + 1) + k];
                unsigned long long xp;
                asm("mov.b64 %0, {%1, %1};" : "=l"(xp) : "f"(xv));
#pragma unroll
                for (int jp = 0; jp < NP; jp++) {
                    asm("fma.rn.f32x2 %0, %1, %2, %0;"
                        : "+l"(acc[i][jp]) : "l"(xp), "l"(wv[jp]));
                }
            }
        }
    }

#pragma unroll
    for (int i = 0; i < TM; i++) {
        int row = row0 + r0 + i;
        if (row >= n) break;
        if (GCNEPI) {
            float di = dinv[row];
            float di2 = di * di;
            float2* hsr = (float2*)(Hs + (size_t)row * DOUT + col0);
            float2* agr = (float2*)(AGG + (size_t)row * DOUT + col0);
#pragma unroll
            for (int jp = 0; jp < NP; jp++) {
                float lo, hi;
                asm("mov.b64 {%0, %1}, %2;" : "=f"(lo), "=f"(hi) : "l"(acc[i][jp]));
                float blo = __ldg(&b[col0 + 2 * jp]);
                float bhi = __ldg(&b[col0 + 2 * jp + 1]);
                hsr[jp] = make_float2(lo * di, hi * di);
                agr[jp] = make_float2(lo * di2 + blo, hi * di2 + bhi);
            }
        } else {
            float2* outr = (float2*)(AGG + (size_t)row * DOUT + col0);
#pragma unroll
            for (int jp = 0; jp < NP; jp++) {
                float lo, hi;
                asm("mov.b64 {%0, %1}, %2;" : "=f"(lo), "=f"(hi) : "l"(acc[i][jp]));
                float blo = __ldg(&b[col0 + 2 * jp]);
                float bhi = __ldg(&b[col0 + 2 * jp + 1]);
                outr[jp] = make_float2(lo + blo, hi + bhi);
            }
        }
    }
}

// ---------------------------------------------------------------------------
// CSR gather-aggregate (agg-after layers):
//   AGG[node] += (sum over incoming src of Hs[src]) * dinv[node]
// AGG pre-holds self-loop + bias. One thread per (node, feature group).
// ---------------------------------------------------------------------------
template <int NV>  // NV = DIM/4
__global__ void agg_csr_v4(const float4* __restrict__ Hs,
                           const int* __restrict__ off,
                           const int* __restrict__ csrc,
                           const float* __restrict__ dinv,
                           float4* __restrict__ AGG, int n) {
    int idx = blockIdx.x * blockDim.x + threadIdx.x;
    if (idx >= n * NV) return;
    int node = idx / NV;
    int g = idx - node * NV;
    int e = __ldg(&off[node]);
    int e1 = __ldg(&off[node + 1]);
    float4 sum = make_float4(0.f, 0.f, 0.f, 0.f);
    for (; e + 1 < e1; e += 2) {
        int s0 = __ldg(&csrc[e]);
        int s1 = __ldg(&csrc[e + 1]);
        float4 h0 = __ldg(&Hs[(size_t)s0 * NV + g]);
        float4 h1 = __ldg(&Hs[(size_t)s1 * NV + g]);
        sum.x += h0.x + h1.x; sum.y += h0.y + h1.y;
        sum.z += h0.z + h1.z; sum.w += h0.w + h1.w;
    }
    if (e < e1) {
        int s0 = __ldg(&csrc[e]);
        float4 h0 = __ldg(&Hs[(size_t)s0 * NV + g]);
        sum.x += h0.x; sum.y += h0.y; sum.z += h0.z; sum.w += h0.w;
    }
    float nd = __ldg(&dinv[node]);
    float4 acc = AGG[(size_t)node * NV + g];
    acc.x = fmaf(sum.x, nd, acc.x);
    acc.y = fmaf(sum.y, nd, acc.y);
    acc.z = fmaf(sum.z, nd, acc.z);
    acc.w = fmaf(sum.w, nd, acc.w);
    AGG[(size_t)node * NV + g] = acc;
}

template <int NV>  // NV = DIM/2 (8B-aligned rows, dim 50)
__global__ void agg_csr_v2(const float2* __restrict__ Hs,
                           const int* __restrict__ off,
                           const int* __restrict__ csrc,
                           const float* __restrict__ dinv,
                           float2* __restrict__ AGG, int n) {
    int idx = blockIdx.x * blockDim.x + threadIdx.x;
    if (idx >= n * NV) return;
    int node = idx / NV;
    int g = idx - node * NV;
    int e = __ldg(&off[node]);
    int e1 = __ldg(&off[node + 1]);
    float2 sum = make_float2(0.f, 0.f);
    for (; e + 1 < e1; e += 2) {
        int s0 = __ldg(&csrc[e]);
        int s1 = __ldg(&csrc[e + 1]);
        float2 h0 = __ldg(&Hs[(size_t)s0 * NV + g]);
        float2 h1 = __ldg(&Hs[(size_t)s1 * NV + g]);
        sum.x += h0.x + h1.x; sum.y += h0.y + h1.y;
    }
    if (e < e1) {
        int s0 = __ldg(&csrc[e]);
        float2 h0 = __ldg(&Hs[(size_t)s0 * NV + g]);
        sum.x += h0.x; sum.y += h0.y;
    }
    float nd = __ldg(&dinv[node]);
    float2 acc = AGG[(size_t)node * NV + g];
    acc.x = fmaf(sum.x, nd, acc.x);
    acc.y = fmaf(sum.y, nd, acc.y);
    AGG[(size_t)node * NV + g] = acc;
}

// ---------------------------------------------------------------------------
// final: logits = leaky(H3) @ Wl + bl, then log_softmax over 10 classes
// ---------------------------------------------------------------------------
__global__ void final_kernel(const float* __restrict__ H,
                             const float* __restrict__ Wl,
                             const float* __restrict__ bl,
                             float* __restrict__ out, int n) {
    __shared__ float Ws[50 * 10];
    __shared__ float bs[10];
    for (int i = threadIdx.x; i < 500; i += blockDim.x) Ws[i] = Wl[i];
    if (threadIdx.x < 10) bs[threadIdx.x] = bl[threadIdx.x];
    __syncthreads();

    int i = blockIdx.x * blockDim.x + threadIdx.x;
    if (i >= n) return;

    float logits[10];
#pragma unroll
    for (int j = 0; j < 10; j++) logits[j] = bs[j];

    const float* hr = H + (size_t)i * 50;
#pragma unroll
    for (int k = 0; k < 50; k++) {
        float v = __ldg(&hr[k]);
        v = (v > 0.0f) ? v : 0.01f * v;
#pragma unroll
        for (int j = 0; j < 10; j++) logits[j] = fmaf(v, Ws[k * 10 + j], logits[j]);
    }

    float mx = logits[0];
#pragma unroll
    for (int j = 1; j < 10; j++) mx = fmaxf(mx, logits[j]);
    float s = 0.0f;
#pragma unroll
    for (int j = 0; j < 10; j++) s += __expf(logits[j] - mx);
    float lse = mx + __logf(s);
#pragma unroll
    for (int j = 0; j < 10; j++) out[(size_t)i * 10 + j] = logits[j] - lse;
}

// ---------------------------------------------------------------------------
// launch
// ---------------------------------------------------------------------------
extern "C" void kernel_launch(void* const* d_in, const int* in_sizes, int n_in,
                              void* d_out, int out_size) {
    const float* x = (const float*)d_in[0];
    const int* edge = (const int*)d_in[1];  // int32 (JAX downcast)
    const float* W1 = (const float*)d_in[2];
    const float* b1 = (const float*)d_in[3];
    const float* W2 = (const float*)d_in[4];
    const float* b2 = (const float*)d_in[5];
    const float* W3 = (const float*)d_in[6];
    const float* b3 = (const float*)d_in[7];
    const float* Wl = (const float*)d_in[8];
    const float* bl = (const float*)d_in[9];
    float* out = (float*)d_out;

    const int n = in_sizes[0] / 64;  // 100000
    const int E = in_sizes[1] / 2;   // 1000000
    const int* src = edge;
    const int* dst = edge + E;

    float *bufA, *bufB, *bufC, *dinv;
    int *deg, *incl, *bsum, *boff, *off, *cur, *csrc;
    cudaGetSymbolAddress((void**)&bufA, g_bufA);
    cudaGetSymbolAddress((void**)&bufB, g_bufB);
    cudaGetSymbolAddress((void**)&bufC, g_bufC);
    cudaGetSymbolAddress((void**)&dinv, g_dinv);
    cudaGetSymbolAddress((void**)&deg, g_deg);
    cudaGetSymbolAddress((void**)&incl, g_incl);
    cudaGetSymbolAddress((void**)&bsum, g_bsum);
    cudaGetSymbolAddress((void**)&boff, g_boff);
    cudaGetSymbolAddress((void**)&off, g_off);
    cudaGetSymbolAddress((void**)&cur, g_cur);
    cudaGetSymbolAddress((void**)&csrc, g_csrc);

    const int T = 256;
    const int nb = cdiv(n, SCAN_B);

    // ---- CSR build (by dst) + dinv ----
    deg_zero<<<cdiv(n, T), T>>>(deg, n);
    deg_hist<<<cdiv(E, T), T>>>(dst, deg, E);
    scan_block<<<nb, SCAN_B>>>(deg, incl, bsum, n);
    scan_bsums<<<1, 128>>>(bsum, boff, nb);
    finish_offsets<<<cdiv(n, T), T>>>(deg, incl, boff, off, cur, dinv, n, E);
    csr_scatter<<<cdiv(E, T), T>>>(src, dst, cur, csrc, E);

    // ---- layer 1: aggregate-first on x (dim 64), then GEMM 64->80 ----
    // agg: x -> Z1 (bufB); gemm: Z1 -> out1 (bufC), plain epilogue
    agg_x_v4<<<cdiv(n * 16, T), T>>>((const float4*)x, off, csrc, dinv,
                                     (float4*)bufB, n);
    gemm_fused<64, 80, 128, 32, 4, 10, 256, false, false>
        <<<cdiv(n, 128), 256>>>(bufB, W1, b1, dinv, bufA, bufC, n);

    // ---- layer 2: 80 -> 40, agg-after ----  X=bufC(leaky), Hs=bufA, AGG=bufB
    gemm_fused<80, 40, 256, 20, 4, 10, 256, true, true>
        <<<cdiv(n, 256), 256>>>(bufC, W2, b2, dinv, bufA, bufB, n);
    agg_csr_v4<10><<<cdiv(n * 10, T), T>>>((const float4*)bufA, off, csrc, dinv,
                                           (float4*)bufB, n);

    // ---- layer 3: 40 -> 50, agg-after ----  X=bufB(leaky), Hs=bufA, AGG=bufC
    gemm_fused<40, 50, 256, 20, 4, 10, 320, true, true>
        <<<cdiv(n, 256), 320>>>(bufB, W3, b3, dinv, bufA, bufC, n);
    agg_csr_v2<25><<<cdiv(n * 25, T), T>>>((const float2*)bufA, off, csrc, dinv,
                                           (float2*)bufC, n);

    // ---- final linear + log_softmax ----
    final_kernel<<<cdiv(n, T), T>>>(bufC, Wl, bl, out, n);
}